// round 3
// baseline (speedup 1.0000x reference)
#include <cuda_runtime.h>
#include <cuda_bf16.h>

// ----------------------------------------------------------------------------
// Problem constants: B=128, T=32, F=2048, H=1024, L=20, WV=300, V=10000
// TF gate order along 4H axis: i, j, f, o ; FORGET_BIAS = 1.0
// ----------------------------------------------------------------------------

#define B_   128
#define T_   32
#define F_   2048
#define H_   1024
#define L_   20
#define WV_  300
#define G4H  4096      // 4*H

// ---------------- device scratch (no runtime allocation allowed) ------------
__device__ float g_xg_enc[(size_t)4096 * 4096];  // [t*128+b][4H] enc input gates (+bias)
__device__ float g_xg_dec[(size_t)2560 * 4096];  // [l*128+b][4H] dec input gates (+bias)
__device__ float g_zp[(size_t)4 * 128 * 4096];   // split-K partials [ks][b][4H]
__device__ float g_h[B_ * H_];                   // hidden state [b][h]
__device__ float g_c[B_ * H_];                   // cell state   [b][h]
__device__ float g_hs[(size_t)L_ * B_ * H_];     // decoder outputs [l*128+b][h]

// ----------------------------------------------------------------------------
// Generic 128x128 SGEMM, 256 threads, 8x8 per thread, BK=8, single-buffered.
// MODE 0: enc XG   A=frames (row remap (b*T+t)), B=enc_kernel,  C=g_xg_enc (+bias)
// MODE 1: dec XG   A=embeddings (gather via caption), B=dec_kernel, C=g_xg_dec (+bias)
// MODE 2: proj     A=g_hs, B=proj_W (ldb=300, N=300 masked), C=d_out (+bias)
// MODE 3: rec step A=g_h (M=128), B=Wh slice, split-K via blockIdx.y, C=g_zp
// ----------------------------------------------------------------------------
template <int MODE>
__global__ void __launch_bounds__(256)
sgemm_k(const float* __restrict__ A, const float* __restrict__ B,
        const float* __restrict__ bias, float* __restrict__ C,
        const int* __restrict__ caption, int Kvalid, int ldb)
{
    const int ntile = blockIdx.x;
    const int mtile = (MODE == 3) ? 0 : blockIdx.y;

    int kBegin = 0, kEnd = Kvalid;
    if (MODE == 3) { kBegin = blockIdx.y * 256; kEnd = kBegin + 256; }

    __shared__ float a_s[8][128];
    __shared__ float b_s[8][128];

    const int tid = threadIdx.x;
    const int tx = tid & 15;        // 0..15 (N direction)
    const int ty = tid >> 4;        // 0..15 (M direction)

    // A-staging ids: 128 rows x 8 k, 4 floats/thread
    const int aM = tid >> 1;            // 0..127
    const int aK = (tid & 1) * 4;       // 0 or 4
    // B-staging ids: 8 k-rows x 128 cols, float4/thread
    const int bK = tid >> 5;            // 0..7
    const int bN = (tid & 31) * 4;      // 0..124

    // A source pointer + row offset
    const float* Ap;
    if (MODE == 3)      Ap = g_h;
    else if (MODE == 2) Ap = g_hs;
    else                Ap = A;

    const int m_a = mtile * 128 + aM;
    size_t aOff;
    if (MODE == 0)      aOff = (size_t)((m_a & 127) * T_ + (m_a >> 7)) * F_; // frames[b][t][*]
    else if (MODE == 1) aOff = (size_t)caption[(m_a & 127) * L_ + (m_a >> 7)] * WV_;
    else                aOff = (size_t)m_a * H_;
    const float* Arow = Ap + aOff;

    // C destination
    float* Cp;
    if (MODE == 0)      Cp = g_xg_enc;
    else if (MODE == 1) Cp = g_xg_dec;
    else if (MODE == 3) Cp = g_zp;
    else                Cp = C;

    float acc[8][8];
#pragma unroll
    for (int i = 0; i < 8; i++)
#pragma unroll
        for (int j = 0; j < 8; j++) acc[i][j] = 0.f;

    for (int kt = kBegin; kt < kEnd; kt += 8) {
        // ---- stage A tile (transposed) ----
        float4 av;
        if (MODE == 1 && kt + 8 > Kvalid) {
            float t0 = (kt + aK + 0 < Kvalid) ? Arow[kt + aK + 0] : 0.f;
            float t1 = (kt + aK + 1 < Kvalid) ? Arow[kt + aK + 1] : 0.f;
            float t2 = (kt + aK + 2 < Kvalid) ? Arow[kt + aK + 2] : 0.f;
            float t3 = (kt + aK + 3 < Kvalid) ? Arow[kt + aK + 3] : 0.f;
            av = make_float4(t0, t1, t2, t3);
        } else {
            av = *reinterpret_cast<const float4*>(Arow + kt + aK);
        }
        a_s[aK + 0][aM] = av.x;
        a_s[aK + 1][aM] = av.y;
        a_s[aK + 2][aM] = av.z;
        a_s[aK + 3][aM] = av.w;

        // ---- stage B tile ----
        {
            const int kb = kt + bK;
            const int col = ntile * 128 + bN;
            float4 bv = make_float4(0.f, 0.f, 0.f, 0.f);
            bool kok = (MODE == 1) ? (kb < Kvalid) : true;
            bool nok = (MODE == 2) ? (col < WV_) : true;
            if (kok && nok)
                bv = *reinterpret_cast<const float4*>(B + (size_t)kb * ldb + col);
            *reinterpret_cast<float4*>(&b_s[bK][bN]) = bv;
        }
        __syncthreads();

        // ---- compute 8 k-substeps ----
#pragma unroll
        for (int kk = 0; kk < 8; kk++) {
            float4 a0 = *reinterpret_cast<const float4*>(&a_s[kk][ty * 8]);
            float4 a1 = *reinterpret_cast<const float4*>(&a_s[kk][ty * 8 + 4]);
            float4 b0 = *reinterpret_cast<const float4*>(&b_s[kk][tx * 8]);
            float4 b1 = *reinterpret_cast<const float4*>(&b_s[kk][tx * 8 + 4]);
            float af[8] = {a0.x, a0.y, a0.z, a0.w, a1.x, a1.y, a1.z, a1.w};
            float bf[8] = {b0.x, b0.y, b0.z, b0.w, b1.x, b1.y, b1.z, b1.w};
#pragma unroll
            for (int i = 0; i < 8; i++)
#pragma unroll
                for (int j = 0; j < 8; j++) acc[i][j] += af[i] * bf[j];
        }
        __syncthreads();
    }

    // ---- store (float4, + bias where applicable) ----
#pragma unroll
    for (int i = 0; i < 8; i++) {
        const int mm = mtile * 128 + ty * 8 + i;
#pragma unroll
        for (int jj = 0; jj < 8; jj += 4) {
            const int nn = ntile * 128 + tx * 8 + jj;
            float4 v = make_float4(acc[i][jj], acc[i][jj + 1], acc[i][jj + 2], acc[i][jj + 3]);
            if (MODE == 0 || MODE == 1) {
                float4 bb = *reinterpret_cast<const float4*>(bias + nn);
                v.x += bb.x; v.y += bb.y; v.z += bb.z; v.w += bb.w;
                *reinterpret_cast<float4*>(&Cp[(size_t)mm * G4H + nn]) = v;
            } else if (MODE == 3) {
                *reinterpret_cast<float4*>(
                    &Cp[((size_t)blockIdx.y * 128 + mm) * G4H + nn]) = v;
            } else { // MODE 2: projection -> out[b][l][v]
                if (nn < WV_) {
                    float4 bb = *reinterpret_cast<const float4*>(bias + nn);
                    v.x += bb.x; v.y += bb.y; v.z += bb.z; v.w += bb.w;
                    const size_t cOff = (size_t)((mm & 127) * L_ + (mm >> 7)) * WV_;
                    *reinterpret_cast<float4*>(&Cp[cOff + nn]) = v;
                }
            }
        }
    }
}

// ----------------------------------------------------------------------------
// Elementwise LSTM gates: combine XG[step] + 4 split-K partials, update c,h.
// ----------------------------------------------------------------------------
__device__ __forceinline__ float sigm(float x) { return 1.f / (1.f + expf(-x)); }

__global__ void __launch_bounds__(256)
gate_kernel(int step, int isDec)
{
    const int idx = blockIdx.x * 256 + threadIdx.x;   // 0 .. 131071
    const int b = idx >> 10;
    const int hh = idx & 1023;

    const float* xg = (isDec ? g_xg_dec : g_xg_enc) + (size_t)step * (B_ * G4H);
    const size_t zb = (size_t)b * G4H + hh;

    float z[4];
#pragma unroll
    for (int g = 0; g < 4; g++) {
        float v = xg[zb + g * H_];
#pragma unroll
        for (int s = 0; s < 4; s++)
            v += g_zp[((size_t)(s * 128 + b)) * G4H + g * H_ + hh];
        z[g] = v;
    }

    float c = g_c[idx];
    float ig = sigm(z[0]);
    float jg = tanhf(z[1]);
    float fg = sigm(z[2] + 1.0f);   // FORGET_BIAS
    float og = sigm(z[3]);
    float cn = c * fg + ig * jg;
    float hn = tanhf(cn) * og;

    g_c[idx] = cn;
    g_h[idx] = hn;
    if (isDec) g_hs[(size_t)step * (B_ * H_) + idx] = hn;
}

__global__ void init_state_kernel()
{
    const int idx = blockIdx.x * 256 + threadIdx.x;
    if (idx < B_ * H_) { g_h[idx] = 0.f; g_c[idx] = 0.f; }
}

// ----------------------------------------------------------------------------
// Launch: all on default stream, kernel launches only (graph-capturable).
// Inputs: frames, caption, embeddings, enc_kernel, enc_bias, dec_kernel,
//         dec_bias, proj_W, proj_b
// ----------------------------------------------------------------------------
extern "C" void kernel_launch(void* const* d_in, const int* in_sizes, int n_in,
                              void* d_out, int out_size)
{
    const float* frames  = (const float*)d_in[0];
    const int*   caption = (const int*)  d_in[1];
    const float* emb     = (const float*)d_in[2];
    const float* encK    = (const float*)d_in[3];
    const float* encB    = (const float*)d_in[4];
    const float* decK    = (const float*)d_in[5];
    const float* decB    = (const float*)d_in[6];
    const float* projW   = (const float*)d_in[7];
    const float* projB   = (const float*)d_in[8];
    float*       out     = (float*)d_out;

    const float* WhEnc = encK + (size_t)F_  * G4H;  // rows F..F+H-1
    const float* WhDec = decK + (size_t)WV_ * G4H;  // rows WV..WV+H-1

    init_state_kernel<<<512, 256>>>();

    // encoder input gates: [4096, 2048] x [2048, 4096] + enc_bias
    sgemm_k<0><<<dim3(32, 32), 256>>>(frames, encK, encB, nullptr, nullptr, F_, G4H);
    // decoder input gates: gather(embeddings) [2560, 300] x [300, 4096] + dec_bias
    sgemm_k<1><<<dim3(32, 20), 256>>>(emb, decK, decB, nullptr, caption, WV_, G4H);

    // encoder recurrence: 32 sequential steps
    for (int t = 0; t < T_; t++) {
        sgemm_k<3><<<dim3(32, 4), 256>>>(nullptr, WhEnc, nullptr, nullptr, nullptr, H_, G4H);
        gate_kernel<<<512, 256>>>(t, 0);
    }
    // decoder recurrence (teacher forcing), init = encoder final state
    for (int l = 0; l < L_; l++) {
        sgemm_k<3><<<dim3(32, 4), 256>>>(nullptr, WhDec, nullptr, nullptr, nullptr, H_, G4H);
        gate_kernel<<<512, 256>>>(l, 1);
    }

    // projection: [2560, 1024] x [1024, 300] + proj_b -> out[b][l][v]
    sgemm_k<2><<<dim3(3, 20), 256>>>(nullptr, projW, projB, out, nullptr, H_, WV_);
}

// round 4
// speedup vs baseline: 3.7752x; 3.7752x over previous
#include <cuda_runtime.h>

// ----------------------------------------------------------------------------
// B=128, T=32, F=2048, H=1024, L=20, WV=300; TF gate order i,j,f,o; FORGET_BIAS=1
// ----------------------------------------------------------------------------
#define B_   128
#define T_   32
#define F_   2048
#define H_   1024
#define L_   20
#define WV_  300
#define G4H  4096
#define NBLK 128            // persistent grid size (<=148 SMs -> co-resident)

// ---------------- device scratch ----------------
__device__ float g_xg_enc[(size_t)4096 * 4096];  // [t*128+b][4H]
__device__ float g_xg_dec[(size_t)2560 * 4096];  // [l*128+b][4H]
__device__ float g_zp[(size_t)4 * 128 * 4096];   // split-K partials [ks][b][4H]
__device__ float g_h[B_ * H_];
__device__ float g_c[B_ * H_];
__device__ float g_hs[(size_t)L_ * B_ * H_];     // [l*128+b][H]
__device__ unsigned g_bar[128];                  // per-epoch barrier counters

// ---------------- helpers ----------------
__device__ __forceinline__ float f2tf(float x) {
    unsigned u;
    asm("cvt.rna.tf32.f32 %0, %1;" : "=r"(u) : "f"(x));
    return __uint_as_float(u);
}

__device__ __forceinline__ void mma8(float* c, const float* a, const float* b) {
    asm volatile(
        "mma.sync.aligned.m16n8k8.row.col.f32.tf32.tf32.f32 "
        "{%0,%1,%2,%3},{%4,%5,%6,%7},{%8,%9},{%0,%1,%2,%3};"
        : "+f"(c[0]), "+f"(c[1]), "+f"(c[2]), "+f"(c[3])
        : "r"(__float_as_uint(a[0])), "r"(__float_as_uint(a[1])),
          "r"(__float_as_uint(a[2])), "r"(__float_as_uint(a[3])),
          "r"(__float_as_uint(b[0])), "r"(__float_as_uint(b[1])));
}

__device__ __forceinline__ float4 add4(float4 a, float4 b) {
    a.x += b.x; a.y += b.y; a.z += b.z; a.w += b.w; return a;
}

__device__ __forceinline__ float sigf(float x) {
    return 1.f / (1.f + __expf(-x));
}

__device__ __forceinline__ void grid_bar(int e) {
    __syncthreads();
    __threadfence();
    if (threadIdx.x == 0) {
        atomicAdd(&g_bar[e], 1u);
        unsigned v;
        do {
            asm volatile("ld.acquire.gpu.u32 %0, [%1];"
                         : "=r"(v) : "l"(&g_bar[e]) : "memory");
        } while (v < NBLK);
    }
    __syncthreads();
}

// ----------------------------------------------------------------------------
// TF32 GEMM, 128x128 block tile, 256 threads (8 warps 2x4), k-chunk 16,
// double-buffered. MODE 0: enc XG. MODE 1: dec XG (emb gather, K=300 masked).
// MODE 2: projection (N=300 masked, remapped output).
// ----------------------------------------------------------------------------
template <int MODE>
__global__ void __launch_bounds__(256, 2)
mm_tf32(const float* __restrict__ A, const float* __restrict__ Bm,
        const float* __restrict__ bias, float* __restrict__ Cout,
        const int* __restrict__ caption, int Kv, int ldb)
{
    __shared__ __align__(16) float a_s[2][128][20];
    __shared__ __align__(16) float b_s[2][16][136];

    const int tid = threadIdx.x;
    const int n0 = blockIdx.x * 128;
    const int mtile = blockIdx.y;

    const int arow = tid >> 2, akq = (tid & 3) * 4;
    const int bkr = tid >> 5, bnq = (tid & 31) * 4;
    const int lane = tid & 31, wid = tid >> 5;
    const int wm = wid >> 2, wn = wid & 3, gid = lane >> 2, tig = lane & 3;

    const float* arp[2];
#pragma unroll
    for (int i = 0; i < 2; i++) {
        const int m = mtile * 128 + i * 64 + arow;
        size_t off;
        if constexpr (MODE == 0)
            off = (size_t)((m & 127) * T_ + (m >> 7)) * F_;     // frames[b][t][*]
        else if constexpr (MODE == 1)
            off = (size_t)caption[(m & 127) * L_ + (m >> 7)] * WV_;
        else
            off = (size_t)m * H_;                                // g_hs row
        arp[i] = ((MODE == 2) ? (const float*)g_hs : A) + off;
    }

    float acc[4][4][4];
#pragma unroll
    for (int a = 0; a < 4; a++)
#pragma unroll
        for (int b = 0; b < 4; b++)
#pragma unroll
            for (int c = 0; c < 4; c++) acc[a][b][c] = 0.f;

    const int NK = (Kv + 15) / 16;

    auto stage = [&](int it, int buf) {
        const int kb = it * 16;
#pragma unroll
        for (int i = 0; i < 2; i++) {
            const int gk = kb + akq;
            float4 v;
            if (MODE == 1 && gk + 3 >= Kv) {
                v.x = (gk + 0 < Kv) ? arp[i][gk + 0] : 0.f;
                v.y = (gk + 1 < Kv) ? arp[i][gk + 1] : 0.f;
                v.z = (gk + 2 < Kv) ? arp[i][gk + 2] : 0.f;
                v.w = (gk + 3 < Kv) ? arp[i][gk + 3] : 0.f;
            } else {
                v = *(const float4*)(arp[i] + gk);
            }
            *(float4*)&a_s[buf][i * 64 + arow][akq] =
                make_float4(f2tf(v.x), f2tf(v.y), f2tf(v.z), f2tf(v.w));
        }
#pragma unroll
        for (int i = 0; i < 2; i++) {
            const int kr = i * 8 + bkr;
            const int gk = kb + kr;
            const int gn = n0 + bnq;
            float4 v = make_float4(0.f, 0.f, 0.f, 0.f);
            const bool kok = (MODE == 1) ? (gk < Kv) : true;
            if (kok) {
                const float* bp = Bm + (size_t)gk * ldb + gn;
                if (MODE == 2 && gn + 3 >= WV_) {
                    if (gn + 0 < WV_) v.x = bp[0];
                    if (gn + 1 < WV_) v.y = bp[1];
                    if (gn + 2 < WV_) v.z = bp[2];
                    if (gn + 3 < WV_) v.w = bp[3];
                } else {
                    v = *(const float4*)bp;
                }
            }
            *(float4*)&b_s[buf][kr][bnq] =
                make_float4(f2tf(v.x), f2tf(v.y), f2tf(v.z), f2tf(v.w));
        }
    };

    stage(0, 0);
    __syncthreads();
    int buf = 0;
    for (int it = 0; it < NK; ++it) {
        if (it + 1 < NK) stage(it + 1, buf ^ 1);
#pragma unroll
        for (int ks = 0; ks < 16; ks += 8) {
            float af[4][4], bf[4][2];
#pragma unroll
            for (int mf = 0; mf < 4; mf++) {
                const int m = wm * 64 + mf * 16 + gid;
                af[mf][0] = a_s[buf][m][ks + tig];
                af[mf][1] = a_s[buf][m + 8][ks + tig];
                af[mf][2] = a_s[buf][m][ks + tig + 4];
                af[mf][3] = a_s[buf][m + 8][ks + tig + 4];
            }
#pragma unroll
            for (int nf = 0; nf < 4; nf++) {
                const int n = wn * 32 + nf * 8 + gid;
                bf[nf][0] = b_s[buf][ks + tig][n];
                bf[nf][1] = b_s[buf][ks + tig + 4][n];
            }
#pragma unroll
            for (int mf = 0; mf < 4; mf++)
#pragma unroll
                for (int nf = 0; nf < 4; nf++) mma8(acc[mf][nf], af[mf], bf[nf]);
        }
        __syncthreads();
        buf ^= 1;
    }

    // epilogue
#pragma unroll
    for (int mf = 0; mf < 4; mf++)
#pragma unroll
        for (int nf = 0; nf < 4; nf++) {
            const int col = n0 + wn * 32 + nf * 8 + 2 * tig;
            const int mrow = mtile * 128 + wm * 64 + mf * 16 + gid;
#pragma unroll
            for (int r = 0; r < 2; r++) {
                const int row = mrow + r * 8;
                const float v0 = acc[mf][nf][2 * r];
                const float v1 = acc[mf][nf][2 * r + 1];
                if constexpr (MODE == 2) {
                    const size_t co = (size_t)((row & 127) * L_ + (row >> 7)) * WV_;
                    if (col < WV_)     Cout[co + col]     = v0 + bias[col];
                    if (col + 1 < WV_) Cout[co + col + 1] = v1 + bias[col + 1];
                } else {
                    float* dst = (MODE == 0 ? g_xg_enc : g_xg_dec)
                                 + (size_t)row * G4H + col;
                    *(float2*)dst = make_float2(v0 + bias[col], v1 + bias[col + 1]);
                }
            }
        }
}

// ----------------------------------------------------------------------------
// Persistent recurrence: 52 steps, 128 blocks (32 N-tiles x 4 K-splits) for the
// h@Wh GEMM, grid barrier, gate phase (block b handles batch row b), barrier.
// ----------------------------------------------------------------------------
__global__ void __launch_bounds__(256)
lstm_persist(const float* __restrict__ WhE, const float* __restrict__ WhD)
{
    __shared__ __align__(16) float a_s[2][128][20];
    __shared__ __align__(16) float b_s[2][16][136];

    const int tid = threadIdx.x, bid = blockIdx.x;
    const int n0 = (bid >> 2) * 128;   // N tile
    const int k0 = (bid & 3) * 256;    // K split
    const int ksplit = bid & 3;

    const int arow = tid >> 2, akq = (tid & 3) * 4;
    const int bkr = tid >> 5, bnq = (tid & 31) * 4;
    const int lane = tid & 31, wid = tid >> 5;
    const int wm = wid >> 2, wn = wid & 3, gid = lane >> 2, tig = lane & 3;

    for (int t = 0; t < T_ + L_; ++t) {
        const bool dec = (t >= T_);
        const int st = dec ? t - T_ : t;
        const float* Wh = dec ? WhD : WhE;
        const float* xg = (dec ? g_xg_dec : g_xg_enc) + (size_t)st * (B_ * G4H);

        // ---- z partial = h[:, k0:k0+256] @ Wh[k0:k0+256, n0:n0+128] ----
        float acc[4][4][4];
#pragma unroll
        for (int a = 0; a < 4; a++)
#pragma unroll
            for (int b = 0; b < 4; b++)
#pragma unroll
                for (int c = 0; c < 4; c++) acc[a][b][c] = 0.f;

        auto stage = [&](int it, int buf) {
            const int kb = k0 + it * 16;
#pragma unroll
            for (int i = 0; i < 2; i++) {
                const int m = i * 64 + arow;
                const float4 v = __ldcg((const float4*)(g_h + (size_t)m * H_ + kb + akq));
                *(float4*)&a_s[buf][m][akq] =
                    make_float4(f2tf(v.x), f2tf(v.y), f2tf(v.z), f2tf(v.w));
            }
#pragma unroll
            for (int i = 0; i < 2; i++) {
                const int kr = i * 8 + bkr;
                const float4 v = *(const float4*)(Wh + (size_t)(kb + kr) * G4H + n0 + bnq);
                *(float4*)&b_s[buf][kr][bnq] =
                    make_float4(f2tf(v.x), f2tf(v.y), f2tf(v.z), f2tf(v.w));
            }
        };

        stage(0, 0);
        __syncthreads();
        int buf = 0;
        for (int it = 0; it < 16; ++it) {
            if (it + 1 < 16) stage(it + 1, buf ^ 1);
#pragma unroll
            for (int ks = 0; ks < 16; ks += 8) {
                float af[4][4], bf[4][2];
#pragma unroll
                for (int mf = 0; mf < 4; mf++) {
                    const int m = wm * 64 + mf * 16 + gid;
                    af[mf][0] = a_s[buf][m][ks + tig];
                    af[mf][1] = a_s[buf][m + 8][ks + tig];
                    af[mf][2] = a_s[buf][m][ks + tig + 4];
                    af[mf][3] = a_s[buf][m + 8][ks + tig + 4];
                }
#pragma unroll
                for (int nf = 0; nf < 4; nf++) {
                    const int n = wn * 32 + nf * 8 + gid;
                    bf[nf][0] = b_s[buf][ks + tig][n];
                    bf[nf][1] = b_s[buf][ks + tig + 4][n];
                }
#pragma unroll
                for (int mf = 0; mf < 4; mf++)
#pragma unroll
                    for (int nf = 0; nf < 4; nf++) mma8(acc[mf][nf], af[mf], bf[nf]);
            }
            __syncthreads();
            buf ^= 1;
        }

        // store z partial to g_zp[ksplit][row][col]
#pragma unroll
        for (int mf = 0; mf < 4; mf++)
#pragma unroll
            for (int nf = 0; nf < 4; nf++) {
                const int col = n0 + wn * 32 + nf * 8 + 2 * tig;
                const int mrow = wm * 64 + mf * 16 + gid;
#pragma unroll
                for (int r = 0; r < 2; r++) {
                    const int row = mrow + r * 8;
                    *(float2*)&g_zp[((size_t)(ksplit * 128 + row)) * G4H + col] =
                        make_float2(acc[mf][nf][2 * r], acc[mf][nf][2 * r + 1]);
                }
            }

        grid_bar(2 * t);

        // ---- gates: this block owns batch row b = bid ----
        {
            const int b = bid;
            const int hh = tid * 4;
            const float* xr = xg + (size_t)b * G4H;
            float4 z[4];
#pragma unroll
            for (int g = 0; g < 4; g++) {
                float4 v = *(const float4*)(xr + g * H_ + hh);
#pragma unroll
                for (int s = 0; s < 4; s++)
                    v = add4(v, __ldcg((const float4*)(
                        g_zp + ((size_t)(s * 128 + b)) * G4H + g * H_ + hh)));
                z[g] = v;
            }
            const float4 cp = *(const float4*)(g_c + b * H_ + hh);
            float4 cn, hn;
            const float* zi = (const float*)&z[0];
            const float* zj = (const float*)&z[1];
            const float* zf = (const float*)&z[2];
            const float* zo = (const float*)&z[3];
            const float* cpp = (const float*)&cp;
            float* cnp = (float*)&cn;
            float* hnp = (float*)&hn;
#pragma unroll
            for (int k = 0; k < 4; k++) {
                const float ig = sigf(zi[k]);
                const float jg = tanhf(zj[k]);
                const float fg = sigf(zf[k] + 1.0f);   // FORGET_BIAS
                const float og = sigf(zo[k]);
                const float cc = cpp[k] * fg + ig * jg;
                cnp[k] = cc;
                hnp[k] = tanhf(cc) * og;
            }
            *(float4*)(g_c + b * H_ + hh) = cn;
            *(float4*)(g_h + b * H_ + hh) = hn;
            if (dec)
                *(float4*)(g_hs + ((size_t)st * B_ + b) * H_ + hh) = hn;
        }

        grid_bar(2 * t + 1);
    }
}

__global__ void init_k()
{
    const int i = blockIdx.x * 256 + threadIdx.x;
    if (i < B_ * H_) { g_h[i] = 0.f; g_c[i] = 0.f; }
    if (i < 128) g_bar[i] = 0u;
}

// ----------------------------------------------------------------------------
extern "C" void kernel_launch(void* const* d_in, const int* in_sizes, int n_in,
                              void* d_out, int out_size)
{
    const float* frames  = (const float*)d_in[0];
    const int*   caption = (const int*)  d_in[1];
    const float* emb     = (const float*)d_in[2];
    const float* encK    = (const float*)d_in[3];
    const float* encB    = (const float*)d_in[4];
    const float* decK    = (const float*)d_in[5];
    const float* decB    = (const float*)d_in[6];
    const float* projW   = (const float*)d_in[7];
    const float* projB   = (const float*)d_in[8];
    float*       out     = (float*)d_out;

    init_k<<<512, 256>>>();

    // encoder input gates: [4096,2048] x [2048,4096] + enc_bias
    mm_tf32<0><<<dim3(32, 32), 256>>>(frames, encK, encB, nullptr, nullptr, F_, G4H);
    // decoder input gates: gather(emb) [2560,300] x [300,4096] + dec_bias
    mm_tf32<1><<<dim3(32, 20), 256>>>(emb, decK, decB, nullptr, caption, WV_, G4H);

    // full recurrence (32 enc + 20 dec steps) in one persistent kernel
    lstm_persist<<<NBLK, 256>>>(encK + (size_t)F_ * G4H, decK + (size_t)WV_ * G4H);

    // projection: [2560,1024] x [1024,300] + proj_b -> out[b][l][wv]
    mm_tf32<2><<<dim3(3, 20), 256>>>(nullptr, projW, projB, out, nullptr, H_, WV_);
}

// round 5
// speedup vs baseline: 3.9449x; 1.0450x over previous
#include <cuda_runtime.h>

// ----------------------------------------------------------------------------
// B=128, T=32, F=2048, H=1024, L=20, WV=300; TF gate order i,j,f,o; FORGET_BIAS=1
// ----------------------------------------------------------------------------
#define B_   128
#define T_   32
#define F_   2048
#define H_   1024
#define L_   20
#define WV_  300
#define G4H  4096
#define NBLK 128            // persistent grid (<=148 SMs -> co-resident)

// ---------------- device scratch ----------------
__device__ float g_xg_enc[(size_t)4096 * 4096];  // [t*128+b][4H]
__device__ float g_xg_dec[(size_t)2560 * 4096];  // [l*128+b][4H]
__device__ float g_zp[(size_t)4 * 128 * 4096];   // split-K partials [ks][b][4H]
__device__ float g_h[B_ * H_];
__device__ float g_c[B_ * H_];
__device__ float g_hs[(size_t)L_ * B_ * H_];     // [l*128+b][H]
__device__ unsigned g_bar[128];                  // per-epoch barrier counters

// ---------------- helpers ----------------
__device__ __forceinline__ float f2tf(float x) {
    unsigned u;
    asm("cvt.rna.tf32.f32 %0, %1;" : "=r"(u) : "f"(x));
    return __uint_as_float(u);
}

__device__ __forceinline__ void mma8(float* c, const float* a, const float* b) {
    asm volatile(
        "mma.sync.aligned.m16n8k8.row.col.f32.tf32.tf32.f32 "
        "{%0,%1,%2,%3},{%4,%5,%6,%7},{%8,%9},{%0,%1,%2,%3};"
        : "+f"(c[0]), "+f"(c[1]), "+f"(c[2]), "+f"(c[3])
        : "r"(__float_as_uint(a[0])), "r"(__float_as_uint(a[1])),
          "r"(__float_as_uint(a[2])), "r"(__float_as_uint(a[3])),
          "r"(__float_as_uint(b[0])), "r"(__float_as_uint(b[1])));
}

__device__ __forceinline__ float2 add2(float2 a, float2 b) {
    a.x += b.x; a.y += b.y; return a;
}

__device__ __forceinline__ float sigf(float x) {
    return 1.f / (1.f + __expf(-x));
}

__device__ __forceinline__ void grid_bar(int e) {
    __syncthreads();
    __threadfence();
    if (threadIdx.x == 0) {
        atomicAdd(&g_bar[e], 1u);
        unsigned v;
        do {
            asm volatile("ld.acquire.gpu.u32 %0, [%1];"
                         : "=r"(v) : "l"(&g_bar[e]) : "memory");
        } while (v < NBLK);
    }
    __syncthreads();
}

// ============================================================================
// Shared compute fragment: 16 warps (4x4), warp tile 32x32, BK=16.
// acc[2][4][4]; a_s stride 20, b_s stride 136 (bank-conflict-free).
// ============================================================================
#define ASTR 20
#define BSTR 136

struct TIds {
    int lane, wid, wm, wn, gid, tig;   // compute ids
    int ar, ak, bk, bn;                // staging ids
};
__device__ __forceinline__ TIds make_ids(int tid) {
    TIds s;
    s.lane = tid & 31; s.wid = tid >> 5;
    s.wm = s.wid >> 2; s.wn = s.wid & 3;
    s.gid = s.lane >> 2; s.tig = s.lane & 3;
    s.ar = tid >> 2;          // 0..127
    s.ak = (tid & 3) * 4;     // 0,4,8,12
    s.bk = tid >> 5;          // 0..15
    s.bn = (tid & 31) * 4;    // 0..124
    return s;
}

__device__ __forceinline__ void compute_bk16(
    const float* a_s, const float* b_s, const TIds& s, float acc[2][4][4])
{
#pragma unroll
    for (int ks = 0; ks < 16; ks += 8) {
        float af[2][4], bf[4][2];
#pragma unroll
        for (int mf = 0; mf < 2; mf++) {
            const int m = s.wm * 32 + mf * 16 + s.gid;
            af[mf][0] = a_s[(m)     * ASTR + ks + s.tig];
            af[mf][1] = a_s[(m + 8) * ASTR + ks + s.tig];
            af[mf][2] = a_s[(m)     * ASTR + ks + s.tig + 4];
            af[mf][3] = a_s[(m + 8) * ASTR + ks + s.tig + 4];
        }
#pragma unroll
        for (int nf = 0; nf < 4; nf++) {
            const int n = s.wn * 32 + nf * 8 + s.gid;
            bf[nf][0] = b_s[(ks + s.tig)     * BSTR + n];
            bf[nf][1] = b_s[(ks + s.tig + 4) * BSTR + n];
        }
#pragma unroll
        for (int mf = 0; mf < 2; mf++)
#pragma unroll
            for (int nf = 0; nf < 4; nf++) mma8(acc[mf][nf], af[mf], bf[nf]);
    }
}

__device__ __forceinline__ float4 tf4(float4 v) {
    return make_float4(f2tf(v.x), f2tf(v.y), f2tf(v.z), f2tf(v.w));
}

// ----------------------------------------------------------------------------
// TF32 GEMM (non-recurrent): MODE 0 enc XG, MODE 1 dec XG (gather, K=300),
// MODE 2 projection (N=300, remapped out).
// ----------------------------------------------------------------------------
template <int MODE>
__global__ void __launch_bounds__(512)
mm_tf32(const float* __restrict__ A, const float* __restrict__ Bm,
        const float* __restrict__ bias, float* __restrict__ Cout,
        const int* __restrict__ caption, int Kv, int ldb)
{
    __shared__ __align__(16) float a_s[2][128 * ASTR];
    __shared__ __align__(16) float b_s[2][16 * BSTR];

    const int tid = threadIdx.x;
    const TIds s = make_ids(tid);
    const int n0 = blockIdx.x * 128;
    const int mtile = blockIdx.y;

    // A row pointer (one row per thread)
    const int m = mtile * 128 + s.ar;
    size_t aoff;
    if constexpr (MODE == 0)
        aoff = (size_t)((m & 127) * T_ + (m >> 7)) * F_;           // frames[b][t][*]
    else if constexpr (MODE == 1)
        aoff = (size_t)caption[(m & 127) * L_ + (m >> 7)] * WV_;   // emb gather
    else
        aoff = (size_t)m * H_;                                      // g_hs row
    const float* arow = ((MODE == 2) ? (const float*)g_hs : A) + aoff;

    float acc[2][4][4];
#pragma unroll
    for (int a = 0; a < 2; a++)
#pragma unroll
        for (int b = 0; b < 4; b++)
#pragma unroll
            for (int c = 0; c < 4; c++) acc[a][b][c] = 0.f;

    const int NK = (Kv + 15) / 16;

    auto stage = [&](int it, int buf) {
        const int kb = it * 16;
        // A: 128 x 16, one float4 per thread (Kv is 4-aligned for all modes)
        {
            const int gk = kb + s.ak;
            float4 v = make_float4(0.f, 0.f, 0.f, 0.f);
            if (MODE != 1 || gk < Kv) v = *(const float4*)(arow + gk);
            *(float4*)&a_s[buf][s.ar * ASTR + s.ak] = tf4(v);
        }
        // B: 16 x 128, one float4 per thread
        {
            const int gk = kb + s.bk;
            const int gn = n0 + s.bn;
            float4 v = make_float4(0.f, 0.f, 0.f, 0.f);
            const bool kok = (MODE == 1) ? (gk < Kv) : true;
            const bool nok = (MODE == 2) ? (gn < WV_) : true;
            if (kok && nok) v = *(const float4*)(Bm + (size_t)gk * ldb + gn);
            *(float4*)&b_s[buf][s.bk * BSTR + s.bn] = tf4(v);
        }
    };

    stage(0, 0);
    __syncthreads();
    int buf = 0;
    for (int it = 0; it < NK; ++it) {
        if (it + 1 < NK) stage(it + 1, buf ^ 1);
        compute_bk16(a_s[buf], b_s[buf], s, acc);
        __syncthreads();
        buf ^= 1;
    }

    // epilogue
#pragma unroll
    for (int mf = 0; mf < 2; mf++)
#pragma unroll
        for (int nf = 0; nf < 4; nf++) {
            const int col = n0 + s.wn * 32 + nf * 8 + 2 * s.tig;
            const int mrow = mtile * 128 + s.wm * 32 + mf * 16 + s.gid;
#pragma unroll
            for (int r = 0; r < 2; r++) {
                const int row = mrow + r * 8;
                const float v0 = acc[mf][nf][2 * r];
                const float v1 = acc[mf][nf][2 * r + 1];
                if constexpr (MODE == 2) {
                    if (col < WV_) {   // 300 even: pair never straddles
                        const size_t co = (size_t)((row & 127) * L_ + (row >> 7)) * WV_;
                        Cout[co + col]     = v0 + bias[col];
                        Cout[co + col + 1] = v1 + bias[col + 1];
                    }
                } else {
                    float* dst = (MODE == 0 ? g_xg_enc : g_xg_dec)
                                 + (size_t)row * G4H + col;
                    *(float2*)dst = make_float2(v0 + bias[col], v1 + bias[col + 1]);
                }
            }
        }
}

// ----------------------------------------------------------------------------
// Persistent recurrence: 52 steps; 128 blocks = 32 N-tiles x 4 K-splits for
// z = h @ Wh; grid barrier; gates (block b owns batch row b); grid barrier.
// ----------------------------------------------------------------------------
__global__ void __launch_bounds__(512)
lstm_persist(const float* __restrict__ WhE, const float* __restrict__ WhD)
{
    __shared__ __align__(16) float a_s[2][128 * ASTR];
    __shared__ __align__(16) float b_s[2][16 * BSTR];

    const int tid = threadIdx.x, bid = blockIdx.x;
    const TIds s = make_ids(tid);
    const int n0 = (bid >> 2) * 128;   // N tile
    const int k0 = (bid & 3) * 256;    // K split
    const int ksplit = bid & 3;

    for (int t = 0; t < T_ + L_; ++t) {
        const bool dec = (t >= T_);
        const int st = dec ? t - T_ : t;
        const float* Wh = dec ? WhD : WhE;
        const float* xg = (dec ? g_xg_dec : g_xg_enc) + (size_t)st * (B_ * G4H);

        float acc[2][4][4];
#pragma unroll
        for (int a = 0; a < 2; a++)
#pragma unroll
            for (int b = 0; b < 4; b++)
#pragma unroll
                for (int c = 0; c < 4; c++) acc[a][b][c] = 0.f;

        auto stage = [&](int it, int buf) {
            const int kb = k0 + it * 16;
            // A = h rows (cross-SM producer -> L2 load)
            const float4 va = __ldcg((const float4*)(g_h + (size_t)s.ar * H_ + kb + s.ak));
            *(float4*)&a_s[buf][s.ar * ASTR + s.ak] = tf4(va);
            // B = Wh slice (read-only weights)
            const float4 vb = *(const float4*)(Wh + (size_t)(kb + s.bk) * G4H + n0 + s.bn);
            *(float4*)&b_s[buf][s.bk * BSTR + s.bn] = tf4(vb);
        };

        stage(0, 0);
        __syncthreads();
        int buf = 0;
        for (int it = 0; it < 16; ++it) {
            if (it + 1 < 16) stage(it + 1, buf ^ 1);
            compute_bk16(a_s[buf], b_s[buf], s, acc);
            __syncthreads();
            buf ^= 1;
        }

        // store z partials
#pragma unroll
        for (int mf = 0; mf < 2; mf++)
#pragma unroll
            for (int nf = 0; nf < 4; nf++) {
                const int col = n0 + s.wn * 32 + nf * 8 + 2 * s.tig;
                const int mrow = s.wm * 32 + mf * 16 + s.gid;
#pragma unroll
                for (int r = 0; r < 2; r++) {
                    const int row = mrow + r * 8;
                    *(float2*)&g_zp[((size_t)(ksplit * 128 + row)) * G4H + col] =
                        make_float2(acc[mf][nf][2 * r], acc[mf][nf][2 * r + 1]);
                }
            }

        grid_bar(2 * t);

        // ---- gates: block b = bid, thread handles 2 h elements ----
        {
            const int b = bid;
            const int hh = tid * 2;
            const float* xr = xg + (size_t)b * G4H;
            float2 z[4];
#pragma unroll
            for (int g = 0; g < 4; g++) {
                float2 v = *(const float2*)(xr + g * H_ + hh);
#pragma unroll
                for (int sp = 0; sp < 4; sp++)
                    v = add2(v, __ldcg((const float2*)(
                        g_zp + ((size_t)(sp * 128 + b)) * G4H + g * H_ + hh)));
                z[g] = v;
            }
            const float2 cp = *(const float2*)(g_c + b * H_ + hh);
            float2 cn, hn;
            {
                const float ig = sigf(z[0].x);
                const float jg = tanhf(z[1].x);
                const float fg = sigf(z[2].x + 1.0f);
                const float og = sigf(z[3].x);
                cn.x = cp.x * fg + ig * jg;
                hn.x = tanhf(cn.x) * og;
            }
            {
                const float ig = sigf(z[0].y);
                const float jg = tanhf(z[1].y);
                const float fg = sigf(z[2].y + 1.0f);
                const float og = sigf(z[3].y);
                cn.y = cp.y * fg + ig * jg;
                hn.y = tanhf(cn.y) * og;
            }
            *(float2*)(g_c + b * H_ + hh) = cn;
            *(float2*)(g_h + b * H_ + hh) = hn;
            if (dec)
                *(float2*)(g_hs + ((size_t)st * B_ + b) * H_ + hh) = hn;
        }

        grid_bar(2 * t + 1);
    }
}

__global__ void init_k()
{
    const int i = blockIdx.x * 256 + threadIdx.x;
    if (i < B_ * H_) { g_h[i] = 0.f; g_c[i] = 0.f; }
    if (i < 128) g_bar[i] = 0u;
}

// ----------------------------------------------------------------------------
extern "C" void kernel_launch(void* const* d_in, const int* in_sizes, int n_in,
                              void* d_out, int out_size)
{
    const float* frames  = (const float*)d_in[0];
    const int*   caption = (const int*)  d_in[1];
    const float* emb     = (const float*)d_in[2];
    const float* encK    = (const float*)d_in[3];
    const float* encB    = (const float*)d_in[4];
    const float* decK    = (const float*)d_in[5];
    const float* decB    = (const float*)d_in[6];
    const float* projW   = (const float*)d_in[7];
    const float* projB   = (const float*)d_in[8];
    float*       out     = (float*)d_out;

    init_k<<<512, 256>>>();

    // encoder input gates: [4096,2048] x [2048,4096] + enc_bias
    mm_tf32<0><<<dim3(32, 32), 512>>>(frames, encK, encB, nullptr, nullptr, F_, G4H);
    // decoder input gates: gather(emb) [2560,300] x [300,4096] + dec_bias
    mm_tf32<1><<<dim3(32, 20), 512>>>(emb, decK, decB, nullptr, caption, WV_, G4H);

    // full recurrence (32 enc + 20 dec steps), one persistent kernel
    lstm_persist<<<NBLK, 512>>>(encK + (size_t)F_ * G4H, decK + (size_t)WV_ * G4H);

    // projection: [2560,1024] x [1024,300] + proj_b -> out[b][l][wv]
    mm_tf32<2><<<dim3(3, 20), 512>>>(nullptr, projW, projB, out, nullptr, H_, WV_);
}

// round 6
// speedup vs baseline: 4.1756x; 1.0585x over previous
#include <cuda_runtime.h>
#include <cstdint>

// ----------------------------------------------------------------------------
// B=128, T=32, F=2048, H=1024, L=20, WV=300; TF gate order i,j,f,o; FORGET_BIAS=1
// ----------------------------------------------------------------------------
#define B_   128
#define T_   32
#define F_   2048
#define H_   1024
#define L_   20
#define WV_  300
#define G4H  4096
#define NBLK 128
#define NSTG 3

// ---------------- device scratch ----------------
__device__ float g_xg_enc[(size_t)4096 * 4096];   // [t*128+b][4H]
__device__ float g_xg_dec[(size_t)2560 * 4096];   // [l*128+b][4H]
__device__ float g_zp[(size_t)128 * 128 * 128];   // [bid][batch 128][gatecol 128]
__device__ float g_hbuf[2][B_ * H_];              // double-buffered h (tf32-rounded)
__device__ float g_hs[(size_t)L_ * B_ * H_];      // decoder outputs
__device__ float g_whE[(size_t)H_ * G4H];         // tf32-rounded Wh (encoder)
__device__ float g_whD[(size_t)H_ * G4H];         // tf32-rounded Wh (decoder)
__device__ unsigned g_flagZ[NBLK * 8];            // padded flags (32B apart)
__device__ unsigned g_flagH[NBLK * 8];

// ---------------- helpers ----------------
__device__ __forceinline__ float f2tf(float x) {
    unsigned u;
    asm("cvt.rna.tf32.f32 %0, %1;" : "=r"(u) : "f"(x));
    return __uint_as_float(u);
}
__device__ __forceinline__ float4 tf4(float4 v) {
    return make_float4(f2tf(v.x), f2tf(v.y), f2tf(v.z), f2tf(v.w));
}
__device__ __forceinline__ void mma8(float* c, const float* a, const float* b) {
    asm volatile(
        "mma.sync.aligned.m16n8k8.row.col.f32.tf32.tf32.f32 "
        "{%0,%1,%2,%3},{%4,%5,%6,%7},{%8,%9},{%0,%1,%2,%3};"
        : "+f"(c[0]), "+f"(c[1]), "+f"(c[2]), "+f"(c[3])
        : "r"(__float_as_uint(a[0])), "r"(__float_as_uint(a[1])),
          "r"(__float_as_uint(a[2])), "r"(__float_as_uint(a[3])),
          "r"(__float_as_uint(b[0])), "r"(__float_as_uint(b[1])));
}
__device__ __forceinline__ float sigf(float x) { return 1.f / (1.f + __expf(-x)); }

__device__ __forceinline__ void cpa16(uint32_t dst, const void* src) {
    asm volatile("cp.async.cg.shared.global [%0], [%1], 16;" :: "r"(dst), "l"(src));
}
#define CP_COMMIT() asm volatile("cp.async.commit_group;")
#define CP_WAIT1()  asm volatile("cp.async.wait_group 1;")

// ============================================================================
// mm_tf32: unchanged from R5 (works; will be replaced by tcgen05 later).
// ============================================================================
#define ASTR 20
#define BSTR 136
struct TIds {
    int lane, wid, wm, wn, gid, tig;
    int ar, ak, bk, bn;
};
__device__ __forceinline__ TIds make_ids(int tid) {
    TIds s;
    s.lane = tid & 31; s.wid = tid >> 5;
    s.wm = s.wid >> 2; s.wn = s.wid & 3;
    s.gid = s.lane >> 2; s.tig = s.lane & 3;
    s.ar = tid >> 2; s.ak = (tid & 3) * 4;
    s.bk = tid >> 5; s.bn = (tid & 31) * 4;
    return s;
}
__device__ __forceinline__ void compute_bk16(
    const float* a_s, const float* b_s, const TIds& s, float acc[2][4][4])
{
#pragma unroll
    for (int ks = 0; ks < 16; ks += 8) {
        float af[2][4], bf[4][2];
#pragma unroll
        for (int mf = 0; mf < 2; mf++) {
            const int m = s.wm * 32 + mf * 16 + s.gid;
            af[mf][0] = a_s[(m)     * ASTR + ks + s.tig];
            af[mf][1] = a_s[(m + 8) * ASTR + ks + s.tig];
            af[mf][2] = a_s[(m)     * ASTR + ks + s.tig + 4];
            af[mf][3] = a_s[(m + 8) * ASTR + ks + s.tig + 4];
        }
#pragma unroll
        for (int nf = 0; nf < 4; nf++) {
            const int n = s.wn * 32 + nf * 8 + s.gid;
            bf[nf][0] = b_s[(ks + s.tig)     * BSTR + n];
            bf[nf][1] = b_s[(ks + s.tig + 4) * BSTR + n];
        }
#pragma unroll
        for (int mf = 0; mf < 2; mf++)
#pragma unroll
            for (int nf = 0; nf < 4; nf++) mma8(acc[mf][nf], af[mf], bf[nf]);
    }
}

template <int MODE>
__global__ void __launch_bounds__(512)
mm_tf32(const float* __restrict__ A, const float* __restrict__ Bm,
        const float* __restrict__ bias, float* __restrict__ Cout,
        const int* __restrict__ caption, int Kv, int ldb)
{
    __shared__ __align__(16) float a_s[2][128 * ASTR];
    __shared__ __align__(16) float b_s[2][16 * BSTR];

    const int tid = threadIdx.x;
    const TIds s = make_ids(tid);
    const int n0 = blockIdx.x * 128;
    const int mtile = blockIdx.y;

    const int m = mtile * 128 + s.ar;
    size_t aoff;
    if constexpr (MODE == 0)
        aoff = (size_t)((m & 127) * T_ + (m >> 7)) * F_;
    else if constexpr (MODE == 1)
        aoff = (size_t)caption[(m & 127) * L_ + (m >> 7)] * WV_;
    else
        aoff = (size_t)m * H_;
    const float* arow = ((MODE == 2) ? (const float*)g_hs : A) + aoff;

    float acc[2][4][4] = {};
    const int NK = (Kv + 15) / 16;

    auto stage = [&](int it, int buf) {
        const int kb = it * 16;
        {
            const int gk = kb + s.ak;
            float4 v = make_float4(0.f, 0.f, 0.f, 0.f);
            if (MODE != 1 || gk < Kv) v = *(const float4*)(arow + gk);
            *(float4*)&a_s[buf][s.ar * ASTR + s.ak] = tf4(v);
        }
        {
            const int gk = kb + s.bk;
            const int gn = n0 + s.bn;
            float4 v = make_float4(0.f, 0.f, 0.f, 0.f);
            const bool kok = (MODE == 1) ? (gk < Kv) : true;
            const bool nok = (MODE == 2) ? (gn < WV_) : true;
            if (kok && nok) v = *(const float4*)(Bm + (size_t)gk * ldb + gn);
            *(float4*)&b_s[buf][s.bk * BSTR + s.bn] = tf4(v);
        }
    };

    stage(0, 0);
    __syncthreads();
    int buf = 0;
    for (int it = 0; it < NK; ++it) {
        if (it + 1 < NK) stage(it + 1, buf ^ 1);
        compute_bk16(a_s[buf], b_s[buf], s, acc);
        __syncthreads();
        buf ^= 1;
    }

#pragma unroll
    for (int mf = 0; mf < 2; mf++)
#pragma unroll
        for (int nf = 0; nf < 4; nf++) {
            const int col = n0 + s.wn * 32 + nf * 8 + 2 * s.tig;
            const int mrow = mtile * 128 + s.wm * 32 + mf * 16 + s.gid;
#pragma unroll
            for (int r = 0; r < 2; r++) {
                const int row = mrow + r * 8;
                const float v0 = acc[mf][nf][2 * r];
                const float v1 = acc[mf][nf][2 * r + 1];
                if constexpr (MODE == 2) {
                    if (col < WV_) {
                        const size_t co = (size_t)((row & 127) * L_ + (row >> 7)) * WV_;
                        Cout[co + col]     = v0 + bias[col];
                        Cout[co + col + 1] = v1 + bias[col + 1];
                    }
                } else {
                    float* dst = (MODE == 0 ? g_xg_enc : g_xg_dec)
                                 + (size_t)row * G4H + col;
                    *(float2*)dst = make_float2(v0 + bias[col], v1 + bias[col + 1]);
                }
            }
        }
}

// ============================================================================
// Persistent recurrence (restructured):
//  block (gid_n = bid>>2, ks = bid&3):
//    GEMM: z-partial [128 batch][gate cols {g*1024 + gid_n*32 ..+32}] over
//          k in [ks*256, ks*256+256), cp.async 3-stage pipeline.
//    group sync (4 blocks) -> gates for batch rows [ks*32..+32) x its 32 h-cols,
//    c in registers, h written tf32-rounded to parity buffer.
//    one full flag barrier -> next step.
// ============================================================================
__global__ void __launch_bounds__(512)
lstm_persist()
{
    __shared__ __align__(16) float sm[NSTG][4096];   // per stage: A[2048] | B[2048]

    const int tid = threadIdx.x, bid = blockIdx.x;
    const int gid_n = bid >> 2, ks = bid & 3;
    const int hc0 = gid_n * 32;
    const int k0 = ks * 256;

    // compute ids
    const int lane = tid & 31, wid = tid >> 5;
    const int wm = wid >> 2, wn = wid & 3;
    const int gid = lane >> 2, tig = lane & 3;
    const int swzA = ((gid >> 1) & 3) << 2;     // A row-swizzle (per-thread const)
    const int swzB = tig * 8;                   // B col-swizzle

    // staging ids (cp.async)
    const int ar = tid >> 2, akq = (tid & 3) * 4;
    const int a_dst = ar * 16 + (akq ^ (((ar >> 1) & 3) << 2));
    const int bk = tid >> 5, bseg = (tid & 31) >> 3, bnn = (tid & 7) * 4;
    const int b_dst = 2048 + bk * 128 + ((bseg * 32 + bnn) ^ ((bk & 3) * 8));
    const size_t b_srcoff = (size_t)bk * G4H + bseg * 1024 + hc0 + bnn;

    const uint32_t smb = (uint32_t)__cvta_generic_to_shared(&sm[0][0]);

    // gate ids: thread owns 2 elements (gb, ghc), (gb, ghc+1)
    const int li = tid * 2, rb = li >> 5, rc = li & 31;
    const int gb = ks * 32 + rb;
    const int ghc = hc0 + rc;
    float2 creg = make_float2(0.f, 0.f);

    for (int t = 0; t < T_ + L_; ++t) {
        const bool dec = (t >= T_);
        const int st = dec ? t - T_ : t;
        const float* wh = dec ? g_whD : g_whE;
        const float* hsrc = g_hbuf[t & 1];
        const float* xg = (dec ? g_xg_dec : g_xg_enc) + (size_t)st * (B_ * G4H);

        float acc[2][4][4] = {};

        auto issue = [&](int sidx) {
            const int kb = k0 + sidx * 16;
            const uint32_t sb = smb + (uint32_t)((sidx % NSTG) * 4096 * 4);
            cpa16(sb + a_dst * 4, hsrc + (size_t)ar * H_ + kb + akq);
            cpa16(sb + b_dst * 4, wh + (size_t)kb * G4H + b_srcoff);
        };

        issue(0); CP_COMMIT();
        issue(1); CP_COMMIT();

        for (int kt = 0; kt < 16; ++kt) {
            CP_WAIT1();            // stage kt resident
            __syncthreads();       // all warps done with buf (kt-1)
            if (kt + 2 < 16) issue(kt + 2);
            CP_COMMIT();

            const float* a_s = &sm[0][0] + (kt % NSTG) * 4096;
            const float* b_s = a_s + 2048;
#pragma unroll
            for (int kss = 0; kss < 16; kss += 8) {
                float af[2][4], bf[4][2];
#pragma unroll
                for (int mf = 0; mf < 2; mf++) {
                    const int m0 = wm * 32 + mf * 16 + gid;
                    const int c0 = (kss + tig) ^ swzA;
                    const int c1 = (kss + tig + 4) ^ swzA;
                    af[mf][0] = a_s[m0 * 16 + c0];
                    af[mf][1] = a_s[(m0 + 8) * 16 + c0];
                    af[mf][2] = a_s[m0 * 16 + c1];
                    af[mf][3] = a_s[(m0 + 8) * 16 + c1];
                }
#pragma unroll
                for (int nf = 0; nf < 4; nf++) {
                    const int n = wn * 32 + nf * 8 + gid;
                    bf[nf][0] = b_s[(kss + tig) * 128 + (n ^ swzB)];
                    bf[nf][1] = b_s[(kss + tig + 4) * 128 + (n ^ swzB)];
                }
#pragma unroll
                for (int mf = 0; mf < 2; mf++)
#pragma unroll
                    for (int nf = 0; nf < 4; nf++) mma8(acc[mf][nf], af[mf], bf[nf]);
            }
        }

        // ---- store z partials: g_zp[bid][row][col] ----
#pragma unroll
        for (int mf = 0; mf < 2; mf++)
#pragma unroll
            for (int nf = 0; nf < 4; nf++) {
                const int col = wn * 32 + nf * 8 + 2 * tig;
                const int mrow = wm * 32 + mf * 16 + gid;
#pragma unroll
                for (int r = 0; r < 2; r++) {
                    const int row = mrow + r * 8;
                    *(float2*)&g_zp[((size_t)bid * 128 + row) * 128 + col] =
                        make_float2(acc[mf][nf][2 * r], acc[mf][nf][2 * r + 1]);
                }
            }

        // ---- group sync (4 blocks sharing gid_n) ----
        __syncthreads();
        __threadfence();
        if (tid == 0) *(volatile unsigned*)&g_flagZ[bid * 8] = (unsigned)(t + 1);
        if (tid < 4) {
            volatile unsigned* f = &g_flagZ[(gid_n * 4 + tid) * 8];
            while (*f < (unsigned)(t + 1)) {}
        }
        __threadfence();
        __syncthreads();

        // ---- gates: batch rows [ks*32..+32) x h-cols [hc0..hc0+32) ----
        {
            float2 z[4];
#pragma unroll
            for (int g = 0; g < 4; g++) {
                float2 v = *(const float2*)(xg + (size_t)gb * G4H + g * 1024 + ghc);
#pragma unroll
                for (int kp = 0; kp < 4; kp++) {
                    const float2 p = __ldcg((const float2*)(
                        g_zp + ((size_t)(gid_n * 4 + kp) * 128 + gb) * 128 + g * 32 + rc));
                    v.x += p.x; v.y += p.y;
                }
                z[g] = v;
            }
            float2 hn;
            {
                const float ig = sigf(z[0].x);
                const float jg = tanhf(z[1].x);
                const float fg = sigf(z[2].x + 1.0f);
                const float og = sigf(z[3].x);
                creg.x = creg.x * fg + ig * jg;
                hn.x = tanhf(creg.x) * og;
            }
            {
                const float ig = sigf(z[0].y);
                const float jg = tanhf(z[1].y);
                const float fg = sigf(z[2].y + 1.0f);
                const float og = sigf(z[3].y);
                creg.y = creg.y * fg + ig * jg;
                hn.y = tanhf(creg.y) * og;
            }
            const float2 ho = make_float2(f2tf(hn.x), f2tf(hn.y));
            *(float2*)(g_hbuf[(t + 1) & 1] + (size_t)gb * H_ + ghc) = ho;
            if (dec)
                *(float2*)(g_hs + ((size_t)st * B_ + gb) * H_ + ghc) = ho;
        }

        // ---- full barrier (flag array) ----
        __syncthreads();
        __threadfence();
        if (tid == 0) *(volatile unsigned*)&g_flagH[bid * 8] = (unsigned)(t + 1);
        if (tid < NBLK) {
            volatile unsigned* f = &g_flagH[tid * 8];
            while (*f < (unsigned)(t + 1)) __nanosleep(64);
        }
        __threadfence();
        __syncthreads();
    }
}

// ---- prep: round Wh weights to tf32 once per launch ----
__global__ void __launch_bounds__(512)
conv_wh(const float* __restrict__ encK, const float* __restrict__ decK)
{
    const size_t i4 = ((size_t)blockIdx.x * 512 + threadIdx.x) * 4;
    if (i4 < (size_t)H_ * G4H) {
        *(float4*)&g_whE[i4] = tf4(*(const float4*)(encK + (size_t)F_  * G4H + i4));
        *(float4*)&g_whD[i4] = tf4(*(const float4*)(decK + (size_t)WV_ * G4H + i4));
    }
}

__global__ void init_k()
{
    const int i = blockIdx.x * 256 + threadIdx.x;
    if (i < B_ * H_) g_hbuf[0][i] = 0.f;
    if (i < NBLK * 8) { g_flagZ[i] = 0u; g_flagH[i] = 0u; }
}

// ----------------------------------------------------------------------------
extern "C" void kernel_launch(void* const* d_in, const int* in_sizes, int n_in,
                              void* d_out, int out_size)
{
    const float* frames  = (const float*)d_in[0];
    const int*   caption = (const int*)  d_in[1];
    const float* emb     = (const float*)d_in[2];
    const float* encK    = (const float*)d_in[3];
    const float* encB    = (const float*)d_in[4];
    const float* decK    = (const float*)d_in[5];
    const float* decB    = (const float*)d_in[6];
    const float* projW   = (const float*)d_in[7];
    const float* projB   = (const float*)d_in[8];
    float*       out     = (float*)d_out;

    init_k<<<512, 256>>>();
    conv_wh<<<2048, 512>>>(encK, decK);

    // encoder input gates: [4096,2048] x [2048,4096] + enc_bias
    mm_tf32<0><<<dim3(32, 32), 512>>>(frames, encK, encB, nullptr, nullptr, F_, G4H);
    // decoder input gates: gather(emb) [2560,300] x [300,4096] + dec_bias
    mm_tf32<1><<<dim3(32, 20), 512>>>(emb, decK, decB, nullptr, caption, WV_, G4H);

    // full recurrence (32 enc + 20 dec), one persistent kernel
    lstm_persist<<<NBLK, 512>>>();

    // projection: [2560,1024] x [1024,300] + proj_b -> out[b][l][wv]
    mm_tf32<2><<<dim3(3, 20), 512>>>(nullptr, projW, projB, out, nullptr, H_, WV_);
}